// round 3
// baseline (speedup 1.0000x reference)
#include <cuda_runtime.h>
#include <cstdint>

// Problem constants
#define N_TOTAL   32768      // 32 * 32 * 32 rows
#define DIM       256        // embedding dim
#define KCODES    1024       // codebook size

// Tiling for the fused distance/argmin kernel
#define BR        64         // rows per CTA
#define BC        128        // codebook cols per k-tile
#define BD        64         // d-slice staged in smem for W
#define TX        16
#define THREADS   256

// Output layout (tuple flattened in order)
#define QOUT_ELEMS   (32 * DIM * 32 * 32)   // 8388608
#define LOSS_ELEMS   N_TOTAL                // 32768

__device__ float g_wsq[KCODES];
__device__ float g_zsq[N_TOTAL];

// ---------------------------------------------------------------------------
// wsq[k] = sum_d w[d][k]^2  (order-insensitive at the precision that matters)
// ---------------------------------------------------------------------------
__global__ void wsq_kernel(const float* __restrict__ w) {
    int k = blockIdx.x * blockDim.x + threadIdx.x;
    if (k >= KCODES) return;
    float s = 0.f;
    for (int d = 0; d < DIM; d++) {
        float v = w[d * KCODES + k];
        s = __fadd_rn(s, __fmul_rn(v, v));
    }
    g_wsq[k] = s;
}

// ---------------------------------------------------------------------------
// zsq[n] = sum_d z[n,d]^2.  By the grid-shift invariance argument the exact
// order is argmin-irrelevant; keep a fast strided-partials + warp tree.
// ---------------------------------------------------------------------------
__global__ void __launch_bounds__(1024)
zsq_kernel(const float* __restrict__ z) {
    __shared__ float sp[32][33];
    const int tx = threadIdx.x;   // hw offset within tile
    const int ty = threadIdx.y;   // partial index (d mod 32)
    const int n0 = blockIdx.x * 32;
    const int b  = n0 >> 10;
    const int hw = (n0 & 1023) + tx;

    const float* zb = z + ((size_t)(b * DIM) << 10) + hw;
    float p = 0.f;
#pragma unroll
    for (int i = 0; i < 8; i++) {
        float v = zb[(size_t)(ty + 32 * i) << 10];
        p = __fadd_rn(p, __fmul_rn(v, v));
    }
    sp[ty][tx] = p;
    __syncthreads();

    float val = sp[tx][ty];
#pragma unroll
    for (int off = 16; off >= 1; off >>= 1)
        val = __fadd_rn(val, __shfl_down_sync(0xffffffffu, val, off));
    if (tx == 0) g_zsq[n0 + ty] = val;
}

// ---------------------------------------------------------------------------
// Fused: fp32 distance GEMM + HLO-exact score bucketing + argmin
//        + gather + straight-through output + losses.
// ---------------------------------------------------------------------------
__global__ void __launch_bounds__(THREADS, 2)
vq_kernel(const float* __restrict__ z, const float* __restrict__ w,
          float* __restrict__ qout, float* __restrict__ loss,
          float* __restrict__ commit, float* __restrict__ embed) {
    extern __shared__ float sm[];
    float* zs = sm;                         // [DIM][BR]  original z
    float* ws = sm + DIM * BR;              // [BD][BC]
    int*   srowidx = (int*)(ws + BD * BC);  // [BR]

    const int tid = threadIdx.x;
    const int tx = tid % TX;
    const int ty = tid / TX;

    const int n0  = blockIdx.x * BR;
    const int b   = n0 >> 10;
    const int hw0 = n0 & 1023;
    const float* zbase = z + ((size_t)(b * DIM) << 10) + hw0;

    // ---- Load z tile ----
    {
        const int F4 = BR / 4;
        for (int i = tid; i < DIM * F4; i += THREADS) {
            int d = i / F4, f = i % F4;
            float4 v = *(const float4*)(zbase + ((size_t)d << 10) + f * 4);
            *(float4*)(zs + d * BR + f * 4) = v;
        }
    }

    float zsqv[4];
#pragma unroll
    for (int i = 0; i < 4; i++) zsqv[i] = g_zsq[n0 + ty * 4 + i];

    float bestv[4];
    int   besti[4];
#pragma unroll
    for (int i = 0; i < 4; i++) { bestv[i] = 3.4e38f; besti[i] = 0; }

    for (int kt = 0; kt < KCODES / BC; kt++) {
        float acc[4][8];
#pragma unroll
        for (int i = 0; i < 4; i++)
#pragma unroll
            for (int j = 0; j < 8; j++) acc[i][j] = 0.f;

        for (int dt = 0; dt < DIM / BD; dt++) {
            __syncthreads();
            {
                const int F4 = BC / 4;
                for (int i = tid; i < BD * F4; i += THREADS) {
                    int dd = i / F4, f = i % F4;
                    *(float4*)(ws + dd * BC + f * 4) =
                        *(const float4*)(w + (size_t)(dt * BD + dd) * KCODES
                                           + kt * BC + f * 4);
                }
            }
            __syncthreads();

#pragma unroll 8
            for (int dd = 0; dd < BD; dd++) {
                const int d = dt * BD + dd;
                float4 zv = *(const float4*)(zs + d * BR + ty * 4);
                float4 w0 = *(const float4*)(ws + dd * BC + tx * 8);
                float4 w1 = *(const float4*)(ws + dd * BC + tx * 8 + 4);
                float zr[4] = {zv.x, zv.y, zv.z, zv.w};
                float wc[8] = {w0.x, w0.y, w0.z, w0.w, w1.x, w1.y, w1.z, w1.w};
#pragma unroll
                for (int i = 0; i < 4; i++)
#pragma unroll
                    for (int j = 0; j < 8; j++)
                        acc[i][j] = __fmaf_rn(zr[i], wc[j], acc[i][j]);
            }
        }

        // s = fl(fl(zsq + wsq) - fl(2*dot))  — exact HLO composition
#pragma unroll
        for (int j = 0; j < 8; j++) {
            const int c = kt * BC + tx * 8 + j;
            const float wq = g_wsq[c];
#pragma unroll
            for (int i = 0; i < 4; i++) {
                float t1 = __fadd_rn(zsqv[i], wq);
                float s  = __fsub_rn(t1, __fmul_rn(2.f, acc[i][j]));
                if (s < bestv[i]) { bestv[i] = s; besti[i] = c; }
            }
        }
    }

    // ---- argmin across the 16 tx lanes (lexicographic (value, index) min) ----
#pragma unroll
    for (int i = 0; i < 4; i++) {
        float v = bestv[i];
        int idx = besti[i];
#pragma unroll
        for (int off = 8; off >= 1; off >>= 1) {
            float v2 = __shfl_xor_sync(0xffffffffu, v, off);
            int   i2 = __shfl_xor_sync(0xffffffffu, idx, off);
            if (v2 < v || (v2 == v && i2 < idx)) { v = v2; idx = i2; }
        }
        if (tx == 0) srowidx[ty * 4 + i] = idx;
    }
    __syncthreads();

    // ---- Epilogue: gather winning code, write q_st + losses ----
    const int r  = tid & 63;
    const int dh = tid >> 6;
    const int kstar = srowidx[r];
    float partial = 0.f;
    float* qbase = qout + ((size_t)(b * DIM) << 10) + hw0;
#pragma unroll 4
    for (int d = dh; d < DIM; d += 4) {
        float wv = __ldg(w + (size_t)d * KCODES + kstar);
        float zv = zs[d * BR + r];
        float diff = __fsub_rn(wv, zv);
        partial = __fmaf_rn(diff, diff, partial);
        qbase[((size_t)d << 10) + r] = __fadd_rn(zv, diff);  // z + (q - z)
    }

    float* part = ws;     // reuse as scratch (256 floats)
    part[tid] = partial;
    __syncthreads();
    if (dh == 0) {
        float mse = (part[r] + part[64 + r] + part[128 + r] + part[192 + r])
                    * (1.0f / DIM);
        int n = n0 + r;
        commit[n] = mse;
        embed[n]  = mse;
        loss[n]   = __fadd_rn(__fmul_rn(0.25f, mse), mse);
    }
}

// ---------------------------------------------------------------------------
extern "C" void kernel_launch(void* const* d_in, const int* in_sizes, int n_in,
                              void* d_out, int out_size) {
    const float* z = (const float*)d_in[0];
    const float* w = (const float*)d_in[1];
    float* out    = (float*)d_out;
    float* qout   = out;
    float* loss   = out + QOUT_ELEMS;
    float* commit = loss + LOSS_ELEMS;
    float* embed  = commit + LOSS_ELEMS;

    wsq_kernel<<<KCODES / 256, 256>>>(w);
    zsq_kernel<<<N_TOTAL / 32, dim3(32, 32)>>>(z);

    const size_t smem_bytes = (size_t)(DIM * BR + BD * BC + BR) * sizeof(float);
    static bool attr_set = false;
    if (!attr_set) {
        cudaFuncSetAttribute(vq_kernel, cudaFuncAttributeMaxDynamicSharedMemorySize,
                             (int)smem_bytes);
        attr_set = true;
    }
    vq_kernel<<<N_TOTAL / BR, THREADS, smem_bytes>>>(z, w, qout, loss, commit, embed);
}

// round 4
// speedup vs baseline: 1.5068x; 1.5068x over previous
#include <cuda_runtime.h>
#include <cstdint>

// Problem constants
#define N_TOTAL   32768      // 32 * 32 * 32 rows
#define DIM       256        // embedding dim
#define KCODES    1024       // codebook size

// Tiling
#define BR        64         // rows per CTA
#define BC        128        // codebook cols per k-tile
#define BD        32         // d-slice staged in smem for W
#define TX        16
#define TY        8
#define THREADS   128
#define ROWS_T    8          // rows per thread

// Output layout (tuple flattened in order)
#define QOUT_ELEMS   (32 * DIM * 32 * 32)   // 8388608
#define LOSS_ELEMS   N_TOTAL                // 32768

__device__ float g_wsq[KCODES];
__device__ float g_zsq[N_TOTAL];

typedef unsigned long long ull;

// Packed fp32x2 FMA (Blackwell FFMA2) — IEEE fp32 per component, 2x rate.
__device__ __forceinline__ void ffma2(ull& acc, ull a, ull b) {
    asm("fma.rn.f32x2 %0, %1, %2, %0;" : "+l"(acc) : "l"(a), "l"(b));
}
__device__ __forceinline__ ull dup2(float x) {
    ull r;
    asm("mov.b64 %0, {%1, %1};" : "=l"(r) : "f"(x));
    return r;
}
__device__ __forceinline__ float2 unpk(ull p) {
    float2 r;
    asm("mov.b64 {%0, %1}, %2;" : "=f"(r.x), "=f"(r.y) : "l"(p));
    return r;
}

// ---------------------------------------------------------------------------
// wsq[k] = sum_d w[d][k]^2
// ---------------------------------------------------------------------------
__global__ void wsq_kernel(const float* __restrict__ w) {
    int k = blockIdx.x * blockDim.x + threadIdx.x;
    if (k >= KCODES) return;
    float s = 0.f;
    for (int d = 0; d < DIM; d++) {
        float v = w[d * KCODES + k];
        s = __fadd_rn(s, __fmul_rn(v, v));
    }
    g_wsq[k] = s;
}

// ---------------------------------------------------------------------------
// zsq[n] = sum_d z[n,d]^2 (grid-shift invariant: exact order irrelevant)
// ---------------------------------------------------------------------------
__global__ void __launch_bounds__(1024)
zsq_kernel(const float* __restrict__ z) {
    __shared__ float sp[32][33];
    const int tx = threadIdx.x;
    const int ty = threadIdx.y;
    const int n0 = blockIdx.x * 32;
    const int b  = n0 >> 10;
    const int hw = (n0 & 1023) + tx;

    const float* zb = z + ((size_t)(b * DIM) << 10) + hw;
    float p = 0.f;
#pragma unroll
    for (int i = 0; i < 8; i++) {
        float v = zb[(size_t)(ty + 32 * i) << 10];
        p = __fadd_rn(p, __fmul_rn(v, v));
    }
    sp[ty][tx] = p;
    __syncthreads();

    float val = sp[tx][ty];
#pragma unroll
    for (int off = 16; off >= 1; off >>= 1)
        val = __fadd_rn(val, __shfl_down_sync(0xffffffffu, val, off));
    if (tx == 0) g_zsq[n0 + ty] = val;
}

// ---------------------------------------------------------------------------
// Fused: fp32x2 distance GEMM + HLO-exact score bucketing + argmin
//        + gather + straight-through output + losses.
// ---------------------------------------------------------------------------
__global__ void __launch_bounds__(THREADS, 2)
vq_kernel(const float* __restrict__ z, const float* __restrict__ w,
          float* __restrict__ qout, float* __restrict__ loss,
          float* __restrict__ commit, float* __restrict__ embed) {
    extern __shared__ float sm[];
    float* zs   = sm;                        // [DIM][BR]   16384 floats
    float* ws   = zs + DIM * BR;             // [BD][BC]     4096 floats
    float* swsq = ws + BD * BC;              // [KCODES]     1024 floats
    int*   srowidx = (int*)(swsq + KCODES);  // [BR]

    const int tid = threadIdx.x;
    const int tx = tid % TX;
    const int ty = tid / TX;

    const int n0  = blockIdx.x * BR;
    const int b   = n0 >> 10;
    const int hw0 = n0 & 1023;
    const float* zbase = z + ((size_t)(b * DIM) << 10) + hw0;

    // ---- Load z tile (zs[d][r], r contiguous) + wsq stage ----
    {
        const int F4 = BR / 4;   // 16 float4 per d
        for (int i = tid; i < DIM * F4; i += THREADS) {
            int d = i / F4, f = i % F4;
            float4 v = *(const float4*)(zbase + ((size_t)d << 10) + f * 4);
            *(float4*)(zs + d * BR + f * 4) = v;
        }
        for (int i = tid; i < KCODES; i += THREADS) swsq[i] = g_wsq[i];
    }

    float zsqv[ROWS_T];
#pragma unroll
    for (int i = 0; i < ROWS_T; i++) zsqv[i] = g_zsq[n0 + ty * ROWS_T + i];

    float bestv[ROWS_T];
    int   besti[ROWS_T];
#pragma unroll
    for (int i = 0; i < ROWS_T; i++) { bestv[i] = 3.4e38f; besti[i] = 0; }

    for (int kt = 0; kt < KCODES / BC; kt++) {
        ull acc[ROWS_T][4];
#pragma unroll
        for (int i = 0; i < ROWS_T; i++)
#pragma unroll
            for (int p = 0; p < 4; p++) acc[i][p] = 0ull;

        for (int dt = 0; dt < DIM / BD; dt++) {
            __syncthreads();
            {
                // load ws[dd][c] = w[(dt*BD+dd)*KCODES + kt*BC + c]
                const int F4 = BC / 4;   // 32 float4 per dd
                for (int i = tid; i < BD * F4; i += THREADS) {
                    int dd = i / F4, f = i % F4;
                    *(float4*)(ws + dd * BC + f * 4) =
                        *(const float4*)(w + (size_t)(dt * BD + dd) * KCODES
                                           + kt * BC + f * 4);
                }
            }
            __syncthreads();

#pragma unroll 4
            for (int dd = 0; dd < BD; dd++) {
                const int d = dt * BD + dd;
                float4 za = *(const float4*)(zs + d * BR + ty * ROWS_T);
                float4 zb2 = *(const float4*)(zs + d * BR + ty * ROWS_T + 4);
                ull zd[ROWS_T];
                zd[0] = dup2(za.x);  zd[1] = dup2(za.y);
                zd[2] = dup2(za.z);  zd[3] = dup2(za.w);
                zd[4] = dup2(zb2.x); zd[5] = dup2(zb2.y);
                zd[6] = dup2(zb2.z); zd[7] = dup2(zb2.w);
                // cols: chunk0 = tx*4 .. +3 ; chunk1 = 64 + tx*4 .. +3
                ulonglong2 wA = *(const ulonglong2*)(ws + dd * BC + tx * 4);
                ulonglong2 wB = *(const ulonglong2*)(ws + dd * BC + 64 + tx * 4);
#pragma unroll
                for (int i = 0; i < ROWS_T; i++) {
                    ffma2(acc[i][0], zd[i], wA.x);
                    ffma2(acc[i][1], zd[i], wA.y);
                    ffma2(acc[i][2], zd[i], wB.x);
                    ffma2(acc[i][3], zd[i], wB.y);
                }
            }
        }

        // s = fl(fl(zsq + wsq) - fl(2*dot))  — exact HLO composition.
        // pair p: chunk = p>>1, h = p&1 -> cols cbase, cbase+1
#pragma unroll
        for (int p = 0; p < 4; p++) {
            const int c0 = kt * BC + (p >> 1) * 64 + tx * 4 + (p & 1) * 2;
            const float wq0 = swsq[c0];
            const float wq1 = swsq[c0 + 1];
#pragma unroll
            for (int i = 0; i < ROWS_T; i++) {
                float2 dv = unpk(acc[i][p]);
                float s0 = __fsub_rn(__fadd_rn(zsqv[i], wq0), __fmul_rn(2.f, dv.x));
                float s1 = __fsub_rn(__fadd_rn(zsqv[i], wq1), __fmul_rn(2.f, dv.y));
                if (s0 < bestv[i]) { bestv[i] = s0; besti[i] = c0; }
                if (s1 < bestv[i]) { bestv[i] = s1; besti[i] = c0 + 1; }
            }
        }
    }

    // ---- argmin across the 16 tx lanes (lexicographic (value, index) min) ----
#pragma unroll
    for (int i = 0; i < ROWS_T; i++) {
        float v = bestv[i];
        int idx = besti[i];
#pragma unroll
        for (int off = 8; off >= 1; off >>= 1) {
            float v2 = __shfl_xor_sync(0xffffffffu, v, off);
            int   i2 = __shfl_xor_sync(0xffffffffu, idx, off);
            if (v2 < v || (v2 == v && i2 < idx)) { v = v2; idx = i2; }
        }
        if (tx == 0) srowidx[ty * ROWS_T + i] = idx;
    }
    __syncthreads();

    // ---- Epilogue: gather winning code, write q_st + losses ----
    const int r  = tid & 63;
    const int dh = tid >> 6;      // 0..1
    const int kstar = srowidx[r];
    float partial = 0.f;
    float* qbase = qout + ((size_t)(b * DIM) << 10) + hw0;
#pragma unroll 4
    for (int d = dh; d < DIM; d += 2) {
        float wv = __ldg(w + (size_t)d * KCODES + kstar);
        float zv = zs[d * BR + r];
        float diff = __fsub_rn(wv, zv);
        partial = __fmaf_rn(diff, diff, partial);
        qbase[((size_t)d << 10) + r] = __fadd_rn(zv, diff);  // z + (q - z)
    }

    float* part = ws;     // reuse as scratch (128 floats)
    part[tid] = partial;
    __syncthreads();
    if (dh == 0) {
        float mse = (part[r] + part[64 + r]) * (1.0f / DIM);
        int n = n0 + r;
        commit[n] = mse;
        embed[n]  = mse;
        loss[n]   = __fadd_rn(__fmul_rn(0.25f, mse), mse);
    }
}

// ---------------------------------------------------------------------------
extern "C" void kernel_launch(void* const* d_in, const int* in_sizes, int n_in,
                              void* d_out, int out_size) {
    const float* z = (const float*)d_in[0];
    const float* w = (const float*)d_in[1];
    float* out    = (float*)d_out;
    float* qout   = out;
    float* loss   = out + QOUT_ELEMS;
    float* commit = loss + LOSS_ELEMS;
    float* embed  = commit + LOSS_ELEMS;

    wsq_kernel<<<KCODES / 256, 256>>>(w);
    zsq_kernel<<<N_TOTAL / 32, dim3(32, 32)>>>(z);

    const size_t smem_bytes =
        (size_t)(DIM * BR + BD * BC + KCODES + BR) * sizeof(float);
    static bool attr_set = false;
    if (!attr_set) {
        cudaFuncSetAttribute(vq_kernel, cudaFuncAttributeMaxDynamicSharedMemorySize,
                             (int)smem_bytes);
        attr_set = true;
    }
    vq_kernel<<<N_TOTAL / BR, THREADS, smem_bytes>>>(z, w, qout, loss, commit, embed);
}